// round 15
// baseline (speedup 1.0000x reference)
#include <cuda_runtime.h>
#include <cuda_bf16.h>
#include <cuda_fp16.h>
#include <math.h>
#include <cstdint>

#define Bn 16384
#define Dn 1024
#define Kn 512
#define Ln 128
#define Hn 64

#define MTILE 128
#define NTILE 128
#define DK    128            // fp8 elems per chunk (128B rows)
#define NCHUNK (Dn / DK)     // 8
#define STAGES 2
#define STAGE_BYTES 32768u   // A(16KB) + B(16KB)

#define CHB_X   ((uint64_t)Bn * 128)   // 2 MB per chunk block
#define CHB_PHI ((uint64_t)Kn * 128)   // 64 KB per chunk block

#define OFF_MBAR (STAGES * STAGE_BYTES)
#define SMEM_REQ (OFF_MBAR + 64 + 128)

#define L2E 1.4426950408889634f
#define SCALE 16.0f
#define SINV (2.0f * L2E / (SCALE * SCALE))

// ---------------- scratch (chunk-major, PRE-SWIZZLED) ----------------
__device__ uint8_t g_phi8[Kn * Dn];
__device__ uint8_t g_x8[Bn * Dn];
__device__ float g_phinorm[Kn];
__device__ float g_xnorm[Bn];
__device__ float g_colsum[Bn];
__device__ int   g_cnt[Bn / NTILE];

// ---------------- helpers ----------------
__device__ __forceinline__ uint32_t smem_u32(const void* p) {
    uint32_t a;
    asm("{ .reg .u64 t; cvta.to.shared.u64 t, %1; cvt.u32.u64 %0, t; }" : "=r"(a) : "l"(p));
    return a;
}

#define LDSM4(r0, r1, r2, r3, addr) \
    asm volatile("ldmatrix.sync.aligned.m8n8.x4.shared.b16 {%0,%1,%2,%3}, [%4];" \
                 : "=r"(r0), "=r"(r1), "=r"(r2), "=r"(r3) : "r"(addr))

// fp8 MMA with f16 accumulator: 2 acc regs (f16x2)
#define MMA16832H(d, a, b0, b1) \
    asm volatile("mma.sync.aligned.m16n8k32.row.col.f16.e4m3.e4m3.f16 " \
                 "{%0,%1}, {%2,%3,%4,%5}, {%6,%7}, {%0,%1};" \
                 : "+r"((d)[0]), "+r"((d)[1]) \
                 : "r"((a)[0]), "r"((a)[1]), "r"((a)[2]), "r"((a)[3]), \
                   "r"(b0), "r"(b1))

#define MBARRIER_INIT(mb, cnt) \
    asm volatile("mbarrier.init.shared.b64 [%0], %1;" :: "r"(mb), "r"(cnt) : "memory")
#define MBARRIER_EXPECT_TX(mb, bytes) \
    asm volatile("mbarrier.arrive.expect_tx.shared.b64 _, [%0], %1;" :: "r"(mb), "r"(bytes) : "memory")
#define MBARRIER_WAIT_PARITY(mb, ph) do {                                        \
    uint32_t _m = (mb); uint32_t _p = (ph); uint32_t _done;                      \
    asm volatile("{\n\t.reg .pred p;\n\t"                                        \
        "mbarrier.try_wait.parity.shared.b64 p, [%1], %2;\n\t"                   \
        "selp.b32 %0, 1, 0, p;\n\t}" : "=r"(_done) : "r"(_m), "r"(_p) : "memory");\
    if (!_done) {                                                                \
        asm volatile("{\n\t.reg .pred P1;\n\t"                                   \
        "WL_%=:\n\t"                                                             \
        "mbarrier.try_wait.parity.shared.b64 P1, [%0], %1, 0x989680;\n\t"        \
        "@P1 bra.uni WD_%=;\n\t"                                                 \
        "bra.uni WL_%=;\n\t"                                                     \
        "WD_%=:\n\t}" :: "r"(_m), "r"(_p) : "memory");                           \
    }                                                                            \
} while (0)

__device__ __forceinline__ void bulk_cp(uint32_t dst, const void* src,
                                        uint32_t bytes, uint32_t mbar) {
    asm volatile(
        "cp.async.bulk.shared::cluster.global.mbarrier::complete_tx::bytes "
        "[%0], [%1], %2, [%3];"
        :: "r"(dst), "l"(src), "r"(bytes), "r"(mbar) : "memory");
}

__device__ __forceinline__ uint32_t pack_e4m3x4(float e0, float e1, float e2, float e3) {
    uint16_t lo, hi;
    asm("cvt.rn.satfinite.e4m3x2.f32 %0, %1, %2;" : "=h"(lo) : "f"(e1), "f"(e0));
    asm("cvt.rn.satfinite.e4m3x2.f32 %0, %1, %2;" : "=h"(hi) : "f"(e3), "f"(e2));
    return (uint32_t)lo | ((uint32_t)hi << 16);
}

// fast 2^t, FFMA-only. deg-4 poly on [-0.5, 0.5]
__device__ __forceinline__ float exp2_fast(float t) {
    t = fmaxf(t, -126.0f);
    const int   i = __float2int_rn(t);
    const float f = t - (float)i;
    float p = fmaf(0.0096181291f, f, 0.0555041087f);
    p = fmaf(p, f, 0.2402265069f);
    p = fmaf(p, f, 0.6931471806f);
    p = fmaf(p, f, 1.0f);
    return p * __int_as_float((i + 127) << 23);
}

// ============================================================
// Kernel 1 (prep): blocks [0, 2048) = x (warp per row, 16B stores);
//                  blocks [2048, 2048+Kn) = phi MLP
// ============================================================
__global__ __launch_bounds__(256) void prep_kernel(
    const float* __restrict__ x,  const float* __restrict__ z,
    const float* __restrict__ W1, const float* __restrict__ b1,
    const float* __restrict__ W2, const float* __restrict__ b2,
    float* __restrict__ out)
{
    const int t = threadIdx.x;

    if (blockIdx.x < Bn / 8) {
        const int lane = t & 31;
        const int b = blockIdx.x * 8 + (t >> 5);
        const float* xr = x + (uint64_t)b * Dn;
        float nrm = 0.0f;
        // each lane: 2 (chunk, group) pairs; 16 floats -> one 16B store
        #pragma unroll
        for (int pp = 0; pp < 2; pp++) {
            const int p = lane + pp * 32;       // 0..63
            const int chunk = p >> 3;
            const int g     = p & 7;
            const float* src = xr + chunk * 128 + g * 16;
            uint4 pk;
            uint32_t* pku = reinterpret_cast<uint32_t*>(&pk);
            #pragma unroll
            for (int q = 0; q < 4; q++) {
                const float4 v = *reinterpret_cast<const float4*>(src + q * 4);
                pku[q] = pack_e4m3x4(v.x * SCALE, v.y * SCALE, v.z * SCALE, v.w * SCALE);
                nrm = fmaf(v.x, v.x, nrm);
                nrm = fmaf(v.y, v.y, nrm);
                nrm = fmaf(v.z, v.z, nrm);
                nrm = fmaf(v.w, v.w, nrm);
            }
            *reinterpret_cast<uint4*>(
                g_x8 + (uint64_t)chunk * CHB_X + (uint64_t)b * 128
                     + (uint32_t)((g ^ (b & 7)) << 4)) = pk;
        }
        #pragma unroll
        for (int off = 16; off > 0; off >>= 1)
            nrm += __shfl_xor_sync(0xffffffffu, nrm, off);
        if (lane == 0) {
            g_xnorm[b] = nrm;
            g_colsum[b] = 0.0f;
            if (b < Bn / NTILE) g_cnt[b] = 0;
            if (b == 0) out[0] = 0.0f;
        }
    } else {
        __shared__ float zrow[Ln];
        __shared__ float hidden[Hn];
        __shared__ float red[256];
        const int k = blockIdx.x - Bn / 8;

        if (t < Ln) zrow[t] = z[k * Ln + t];
        __syncthreads();

        if (t < Hn) {
            float acc = b1[t];
            #pragma unroll 8
            for (int l = 0; l < Ln; l++)
                acc = fmaf(zrow[l], W1[l * Hn + t], acc);
            hidden[t] = fmaxf(acc, 0.0f);
        }
        __syncthreads();

        const int d0 = t * 4;
        float4 acc = make_float4(b2[d0], b2[d0 + 1], b2[d0 + 2], b2[d0 + 3]);
        #pragma unroll 8
        for (int h = 0; h < Hn; h++) {
            const float hv = hidden[h];
            const float4 w = *reinterpret_cast<const float4*>(W2 + h * Dn + d0);
            acc.x = fmaf(hv, w.x, acc.x);
            acc.y = fmaf(hv, w.y, acc.y);
            acc.z = fmaf(hv, w.z, acc.z);
            acc.w = fmaf(hv, w.w, acc.w);
        }
        {
            const int chunk = t >> 5;
            const uint32_t rowoff = (((((t >> 2) & 7) ^ (k & 7)) << 4) | ((t & 3) << 2));
            *reinterpret_cast<uint32_t*>(
                g_phi8 + (uint64_t)chunk * CHB_PHI + (uint64_t)k * 128 + rowoff) =
                pack_e4m3x4(acc.x * SCALE, acc.y * SCALE, acc.z * SCALE, acc.w * SCALE);
        }

        red[t] = acc.x * acc.x + acc.y * acc.y + acc.z * acc.z + acc.w * acc.w;
        __syncthreads();
        for (int s = 128; s > 0; s >>= 1) {
            if (t < s) red[t] += red[t + s];
            __syncthreads();
        }
        if (t == 0) g_phinorm[k] = red[0];
    }
}

// ============================================================
// Kernel 2 (main): fp8 mma (f16 acc) GEMM 128x128, 2-stage
//   bulk-TMA double buffer, 3 CTAs/SM, single barrier per chunk
// ============================================================
__global__ __launch_bounds__(256, 3) void main_kernel(float* __restrict__ out)
{
    extern __shared__ char smem[];
    const uint32_t Sal = (smem_u32(smem) + 127u) & ~127u;
    const uint32_t MB  = Sal + OFF_MBAR;

    const int t    = threadIdx.x;
    const int lane = t & 31;
    const int wid  = t >> 5;
    const int b_base = blockIdx.x * NTILE;
    const int k_base = blockIdx.y * MTILE;

    const int m_off = (wid & 1) * 64;
    const int n_off = (wid >> 1) * 32;

    const uint8_t* srcA = g_phi8 + (uint64_t)k_base * 128;
    const uint8_t* srcB = g_x8   + (uint64_t)b_base * 128;

    if (t == 0) {
        MBARRIER_INIT(MB + 0, 1);
        MBARRIER_INIT(MB + 8, 1);
        asm volatile("fence.proxy.async.shared::cta;" ::: "memory");
    }
    __syncthreads();

    // prologue: stage chunk 0 into buffer 0
    if (t == 0) {
        MBARRIER_EXPECT_TX(MB + 0, STAGE_BYTES);
        bulk_cp(Sal,          srcA, 16384u, MB + 0);
        bulk_cp(Sal + 16384u, srcB, 16384u, MB + 0);
    }

    // ---- loop-invariant LDSM base offsets ----
    uint32_t a_base[4], b_base2[2];
    {
        const int hi = lane >> 4;
        #pragma unroll
        for (int im = 0; im < 4; im++) {
            const int arow = m_off + im * 16 + (lane & 15);
            const int r = arow & 7;
            a_base[im] = (uint32_t)(arow * 128 + ((hi ^ (r & 1)) << 4) + ((r & 6) << 4));
        }
        const int g  = lane >> 3;
        const int rb = lane & 7;
        #pragma unroll
        for (int in_ = 0; in_ < 2; in_++) {
            const int nrow = n_off + in_ * 16 + ((g >> 1) << 3) + rb;
            b_base2[in_] = (uint32_t)(nrow * 128 + (((g & 1) ^ (rb & 1)) << 4) + ((rb & 6) << 4));
        }
    }

    // f16x2 accumulators
    uint32_t acch[4][4][2];
    #pragma unroll
    for (int i = 0; i < 4; i++)
        #pragma unroll
        for (int j = 0; j < 4; j++) { acch[i][j][0] = 0u; acch[i][j][1] = 0u; }

    int ph0 = 0, ph1 = 0;

    for (int c = 0; c < NCHUNK; c++) {
        const int s = c & 1;
        if (s == 0) { MBARRIER_WAIT_PARITY(MB + 0, (uint32_t)ph0); ph0 ^= 1; }
        else        { MBARRIER_WAIT_PARITY(MB + 8, (uint32_t)ph1); ph1 ^= 1; }
        // single barrier per chunk: passing it proves every warp finished
        // chunk c-1's MMAs (program order), so refilling stage (c+1)&1 is safe
        __syncthreads();

        if (c + 1 < NCHUNK && t == 0) {
            const int sn_ = (c + 1) & 1;
            const uint32_t st = Sal + (uint32_t)sn_ * STAGE_BYTES;
            MBARRIER_EXPECT_TX(MB + sn_ * 8, STAGE_BYTES);
            bulk_cp(st,          srcA + (uint64_t)(c + 1) * CHB_PHI, 16384u, MB + sn_ * 8);
            bulk_cp(st + 16384u, srcB + (uint64_t)(c + 1) * CHB_X,   16384u, MB + sn_ * 8);
        }

        const uint32_t As = Sal + (uint32_t)s * STAGE_BYTES;
        uint32_t aaddr[4], baddr[2];
        #pragma unroll
        for (int im = 0; im < 4; im++) aaddr[im] = As + a_base[im];
        #pragma unroll
        for (int in_ = 0; in_ < 2; in_++) baddr[in_] = As + 16384u + b_base2[in_];

        #pragma unroll
        for (int ks = 0; ks < 4; ks++) {
            const uint32_t kx = (uint32_t)ks << 5;
            uint32_t a[4][4];
            #pragma unroll
            for (int im = 0; im < 4; im++)
                LDSM4(a[im][0], a[im][1], a[im][2], a[im][3], aaddr[im] ^ kx);
            uint32_t b[8];
            #pragma unroll
            for (int in_ = 0; in_ < 2; in_++)
                LDSM4(b[in_ * 4 + 0], b[in_ * 4 + 1], b[in_ * 4 + 2], b[in_ * 4 + 3],
                      baddr[in_] ^ kx);
            #pragma unroll
            for (int im = 0; im < 4; im++)
                #pragma unroll
                for (int ing = 0; ing < 4; ing++)
                    MMA16832H(acch[im][ing], a[im], b[ing * 2], b[ing * 2 + 1]);
        }
    }

    // ---------------- fused epilogue ----------------
    float pnl[4], pnh[4];
    #pragma unroll
    for (int im = 0; im < 4; im++) {
        pnl[im] = g_phinorm[k_base + m_off + im * 16 + (lane >> 2)] * L2E;
        pnh[im] = g_phinorm[k_base + m_off + im * 16 + (lane >> 2) + 8] * L2E;
    }
    float xnv[4][2];
    #pragma unroll
    for (int ing = 0; ing < 4; ing++)
        #pragma unroll
        for (int j = 0; j < 2; j++)
            xnv[ing][j] = g_xnorm[b_base + n_off + ing * 8 + (lane & 3) * 2 + j] * L2E;

    float sn[4][2];
    #pragma unroll
    for (int ing = 0; ing < 4; ing++) { sn[ing][0] = 0.0f; sn[ing][1] = 0.0f; }

    #pragma unroll
    for (int im = 0; im < 4; im++) {
        #pragma unroll
        for (int ing = 0; ing < 4; ing++) {
            const float2 v0 = __half22float2(*reinterpret_cast<__half2*>(&acch[im][ing][0]));
            const float2 v1 = __half22float2(*reinterpret_cast<__half2*>(&acch[im][ing][1]));
            sn[ing][0] += exp2_fast(fmaf(SINV, v0.x, -(pnl[im] + xnv[ing][0])));
            sn[ing][1] += exp2_fast(fmaf(SINV, v0.y, -(pnl[im] + xnv[ing][1])));
            sn[ing][0] += exp2_fast(fmaf(SINV, v1.x, -(pnh[im] + xnv[ing][0])));
            sn[ing][1] += exp2_fast(fmaf(SINV, v1.y, -(pnh[im] + xnv[ing][1])));
        }
    }
    #pragma unroll
    for (int off = 4; off < 32; off <<= 1)
        #pragma unroll
        for (int ing = 0; ing < 4; ing++)
            #pragma unroll
            for (int j = 0; j < 2; j++)
                sn[ing][j] += __shfl_xor_sync(0xffffffffu, sn[ing][j], off);

    if (lane < 4) {
        #pragma unroll
        for (int ing = 0; ing < 4; ing++)
            #pragma unroll
            for (int j = 0; j < 2; j++)
                atomicAdd(&g_colsum[b_base + n_off + ing * 8 + lane * 2 + j], sn[ing][j]);
    }

    // ---- last CTA of this b-slice finalizes its 128 columns ----
    __shared__ int is_last;
    __threadfence();
    if (t == 0) {
        const int old = atomicAdd(&g_cnt[blockIdx.x], 1);
        is_last = (old == (Kn / MTILE) - 1);
    }
    __syncthreads();
    if (is_last && t < NTILE) {
        float s = __logf(g_colsum[b_base + t] * (1.0f / (float)Kn) + 1e-9f)
                  * (1.0f / (float)Bn);
        #pragma unroll
        for (int off = 16; off > 0; off >>= 1)
            s += __shfl_xor_sync(0xffffffffu, s, off);
        if (lane == 0) atomicAdd(out, s);
    }
}

// ============================================================
extern "C" void kernel_launch(void* const* d_in, const int* in_sizes, int n_in,
                              void* d_out, int out_size)
{
    const float* x  = (const float*)d_in[0];
    const float* z  = (const float*)d_in[1];
    const float* W1 = (const float*)d_in[2];
    const float* b1 = (const float*)d_in[3];
    const float* W2 = (const float*)d_in[4];
    const float* b2 = (const float*)d_in[5];
    float* out = (float*)d_out;

    static int smem_set = 0;
    if (!smem_set) {
        cudaFuncSetAttribute(main_kernel, cudaFuncAttributeMaxDynamicSharedMemorySize,
                             SMEM_REQ);
        smem_set = 1;
    }

    prep_kernel<<<Bn / 8 + Kn, 256>>>(x, z, W1, b1, W2, b2, out);
    dim3 grid(Bn / NTILE, Kn / MTILE);   // (128, 4)
    main_kernel<<<grid, 256, SMEM_REQ>>>(out);
}

// round 16
// speedup vs baseline: 1.0414x; 1.0414x over previous
#include <cuda_runtime.h>
#include <cuda_bf16.h>
#include <cuda_fp16.h>
#include <math.h>
#include <cstdint>

#define Bn 16384
#define Dn 1024
#define Kn 512
#define Ln 128
#define Hn 64

#define MTILE 128
#define NTILE 128
#define DK    128            // fp8 elems per chunk (128B rows)
#define NCHUNK (Dn / DK)     // 8
#define STAGES 2
#define STAGE_BYTES 32768u   // A(16KB) + B(16KB)

#define CHB_X   ((uint64_t)Bn * 128)   // 2 MB per chunk block
#define CHB_PHI ((uint64_t)Kn * 128)   // 64 KB per chunk block

#define OFF_MBAR (STAGES * STAGE_BYTES)
#define SMEM_REQ (OFF_MBAR + 64 + 128)

#define L2E 1.4426950408889634f
#define SCALE 16.0f
#define SINV (2.0f * L2E / (SCALE * SCALE))

// ---------------- scratch (chunk-major, PRE-SWIZZLED) ----------------
__device__ uint8_t g_phi8[Kn * Dn];
__device__ uint8_t g_x8[Bn * Dn];
__device__ float g_phinorm[Kn];
__device__ float g_xnorm[Bn];
__device__ float g_colsum[Bn];
__device__ int   g_cnt[Bn / NTILE];

// ---------------- helpers ----------------
__device__ __forceinline__ uint32_t smem_u32(const void* p) {
    uint32_t a;
    asm("{ .reg .u64 t; cvta.to.shared.u64 t, %1; cvt.u32.u64 %0, t; }" : "=r"(a) : "l"(p));
    return a;
}

#define LDSM4(r0, r1, r2, r3, addr) \
    asm volatile("ldmatrix.sync.aligned.m8n8.x4.shared.b16 {%0,%1,%2,%3}, [%4];" \
                 : "=r"(r0), "=r"(r1), "=r"(r2), "=r"(r3) : "r"(addr))

// fp8 MMA with f16 accumulator: 2 acc regs (f16x2)
#define MMA16832H(d, a, b0, b1) \
    asm volatile("mma.sync.aligned.m16n8k32.row.col.f16.e4m3.e4m3.f16 " \
                 "{%0,%1}, {%2,%3,%4,%5}, {%6,%7}, {%0,%1};" \
                 : "+r"((d)[0]), "+r"((d)[1]) \
                 : "r"((a)[0]), "r"((a)[1]), "r"((a)[2]), "r"((a)[3]), \
                   "r"(b0), "r"(b1))

#define MBARRIER_INIT(mb, cnt) \
    asm volatile("mbarrier.init.shared.b64 [%0], %1;" :: "r"(mb), "r"(cnt) : "memory")
#define MBARRIER_EXPECT_TX(mb, bytes) \
    asm volatile("mbarrier.arrive.expect_tx.shared.b64 _, [%0], %1;" :: "r"(mb), "r"(bytes) : "memory")
#define MBARRIER_WAIT_PARITY(mb, ph) do {                                        \
    uint32_t _m = (mb); uint32_t _p = (ph); uint32_t _done;                      \
    asm volatile("{\n\t.reg .pred p;\n\t"                                        \
        "mbarrier.try_wait.parity.shared.b64 p, [%1], %2;\n\t"                   \
        "selp.b32 %0, 1, 0, p;\n\t}" : "=r"(_done) : "r"(_m), "r"(_p) : "memory");\
    if (!_done) {                                                                \
        asm volatile("{\n\t.reg .pred P1;\n\t"                                   \
        "WL_%=:\n\t"                                                             \
        "mbarrier.try_wait.parity.shared.b64 P1, [%0], %1, 0x989680;\n\t"        \
        "@P1 bra.uni WD_%=;\n\t"                                                 \
        "bra.uni WL_%=;\n\t"                                                     \
        "WD_%=:\n\t}" :: "r"(_m), "r"(_p) : "memory");                           \
    }                                                                            \
} while (0)

__device__ __forceinline__ void bulk_cp(uint32_t dst, const void* src,
                                        uint32_t bytes, uint32_t mbar) {
    asm volatile(
        "cp.async.bulk.shared::cluster.global.mbarrier::complete_tx::bytes "
        "[%0], [%1], %2, [%3];"
        :: "r"(dst), "l"(src), "r"(bytes), "r"(mbar) : "memory");
}

__device__ __forceinline__ uint32_t pack_e4m3x4(float e0, float e1, float e2, float e3) {
    uint16_t lo, hi;
    asm("cvt.rn.satfinite.e4m3x2.f32 %0, %1, %2;" : "=h"(lo) : "f"(e1), "f"(e0));
    asm("cvt.rn.satfinite.e4m3x2.f32 %0, %1, %2;" : "=h"(hi) : "f"(e3), "f"(e2));
    return (uint32_t)lo | ((uint32_t)hi << 16);
}

// fast 2^t, FFMA-only. deg-4 poly on [-0.5, 0.5]
__device__ __forceinline__ float exp2_fast(float t) {
    t = fmaxf(t, -126.0f);
    const int   i = __float2int_rn(t);
    const float f = t - (float)i;
    float p = fmaf(0.0096181291f, f, 0.0555041087f);
    p = fmaf(p, f, 0.2402265069f);
    p = fmaf(p, f, 0.6931471806f);
    p = fmaf(p, f, 1.0f);
    return p * __int_as_float((i + 127) << 23);
}

// ============================================================
// Kernel 1 (prep): blocks [0, 2048) = x (warp per row, COALESCED
//   4B stores — one 128B transaction per warp-iteration);
//   blocks [2048, 2048+Kn) = phi MLP
// ============================================================
__global__ __launch_bounds__(256) void prep_kernel(
    const float* __restrict__ x,  const float* __restrict__ z,
    const float* __restrict__ W1, const float* __restrict__ b1,
    const float* __restrict__ W2, const float* __restrict__ b2,
    float* __restrict__ out)
{
    const int t = threadIdx.x;

    if (blockIdx.x < Bn / 8) {
        const int lane = t & 31;
        const int b = blockIdx.x * 8 + (t >> 5);
        const float* xr = x + (uint64_t)b * Dn;
        const uint32_t rowoff = ((((lane >> 2) ^ (b & 7)) << 4) | ((lane & 3) << 2));
        uint8_t* xo = g_x8 + (uint64_t)b * 128 + rowoff;
        float nrm = 0.0f;
        #pragma unroll
        for (int i = 0; i < 8; i++) {
            const float4 v = *reinterpret_cast<const float4*>(xr + i * 128 + lane * 4);
            *reinterpret_cast<uint32_t*>(xo + i * CHB_X) =
                pack_e4m3x4(v.x * SCALE, v.y * SCALE, v.z * SCALE, v.w * SCALE);
            nrm = fmaf(v.x, v.x, nrm);
            nrm = fmaf(v.y, v.y, nrm);
            nrm = fmaf(v.z, v.z, nrm);
            nrm = fmaf(v.w, v.w, nrm);
        }
        #pragma unroll
        for (int off = 16; off > 0; off >>= 1)
            nrm += __shfl_xor_sync(0xffffffffu, nrm, off);
        if (lane == 0) {
            g_xnorm[b] = nrm;
            g_colsum[b] = 0.0f;
            if (b < Bn / NTILE) g_cnt[b] = 0;
            if (b == 0) out[0] = 0.0f;
        }
    } else {
        __shared__ float zrow[Ln];
        __shared__ float hidden[Hn];
        __shared__ float red[256];
        const int k = blockIdx.x - Bn / 8;

        if (t < Ln) zrow[t] = z[k * Ln + t];
        __syncthreads();

        if (t < Hn) {
            float acc = b1[t];
            #pragma unroll 8
            for (int l = 0; l < Ln; l++)
                acc = fmaf(zrow[l], W1[l * Hn + t], acc);
            hidden[t] = fmaxf(acc, 0.0f);
        }
        __syncthreads();

        const int d0 = t * 4;
        float4 acc = make_float4(b2[d0], b2[d0 + 1], b2[d0 + 2], b2[d0 + 3]);
        #pragma unroll 8
        for (int h = 0; h < Hn; h++) {
            const float hv = hidden[h];
            const float4 w = *reinterpret_cast<const float4*>(W2 + h * Dn + d0);
            acc.x = fmaf(hv, w.x, acc.x);
            acc.y = fmaf(hv, w.y, acc.y);
            acc.z = fmaf(hv, w.z, acc.z);
            acc.w = fmaf(hv, w.w, acc.w);
        }
        {
            const int chunk = t >> 5;
            const uint32_t rowoff = (((((t >> 2) & 7) ^ (k & 7)) << 4) | ((t & 3) << 2));
            *reinterpret_cast<uint32_t*>(
                g_phi8 + (uint64_t)chunk * CHB_PHI + (uint64_t)k * 128 + rowoff) =
                pack_e4m3x4(acc.x * SCALE, acc.y * SCALE, acc.z * SCALE, acc.w * SCALE);
        }

        red[t] = acc.x * acc.x + acc.y * acc.y + acc.z * acc.z + acc.w * acc.w;
        __syncthreads();
        for (int s = 128; s > 0; s >>= 1) {
            if (t < s) red[t] += red[t + s];
            __syncthreads();
        }
        if (t == 0) g_phinorm[k] = red[0];
    }
}

// ============================================================
// Kernel 2 (main): fp8 mma (f16 acc) GEMM 128x128, 2-stage
//   bulk-TMA double buffer, 3 CTAs/SM, single barrier per chunk
// ============================================================
__global__ __launch_bounds__(256, 3) void main_kernel(float* __restrict__ out)
{
    extern __shared__ char smem[];
    const uint32_t Sal = (smem_u32(smem) + 127u) & ~127u;
    const uint32_t MB  = Sal + OFF_MBAR;

    const int t    = threadIdx.x;
    const int lane = t & 31;
    const int wid  = t >> 5;
    const int b_base = blockIdx.x * NTILE;
    const int k_base = blockIdx.y * MTILE;

    const int m_off = (wid & 1) * 64;
    const int n_off = (wid >> 1) * 32;

    const uint8_t* srcA = g_phi8 + (uint64_t)k_base * 128;
    const uint8_t* srcB = g_x8   + (uint64_t)b_base * 128;

    if (t == 0) {
        MBARRIER_INIT(MB + 0, 1);
        MBARRIER_INIT(MB + 8, 1);
        asm volatile("fence.proxy.async.shared::cta;" ::: "memory");
    }
    __syncthreads();

    // prologue: stage chunk 0 into buffer 0
    if (t == 0) {
        MBARRIER_EXPECT_TX(MB + 0, STAGE_BYTES);
        bulk_cp(Sal,          srcA, 16384u, MB + 0);
        bulk_cp(Sal + 16384u, srcB, 16384u, MB + 0);
    }

    // ---- loop-invariant LDSM base offsets ----
    uint32_t a_base[4], b_base2[2];
    {
        const int hi = lane >> 4;
        #pragma unroll
        for (int im = 0; im < 4; im++) {
            const int arow = m_off + im * 16 + (lane & 15);
            const int r = arow & 7;
            a_base[im] = (uint32_t)(arow * 128 + ((hi ^ (r & 1)) << 4) + ((r & 6) << 4));
        }
        const int g  = lane >> 3;
        const int rb = lane & 7;
        #pragma unroll
        for (int in_ = 0; in_ < 2; in_++) {
            const int nrow = n_off + in_ * 16 + ((g >> 1) << 3) + rb;
            b_base2[in_] = (uint32_t)(nrow * 128 + (((g & 1) ^ (rb & 1)) << 4) + ((rb & 6) << 4));
        }
    }

    // f16x2 accumulators
    uint32_t acch[4][4][2];
    #pragma unroll
    for (int i = 0; i < 4; i++)
        #pragma unroll
        for (int j = 0; j < 4; j++) { acch[i][j][0] = 0u; acch[i][j][1] = 0u; }

    int ph0 = 0, ph1 = 0;

    for (int c = 0; c < NCHUNK; c++) {
        const int s = c & 1;
        if (s == 0) { MBARRIER_WAIT_PARITY(MB + 0, (uint32_t)ph0); ph0 ^= 1; }
        else        { MBARRIER_WAIT_PARITY(MB + 8, (uint32_t)ph1); ph1 ^= 1; }
        // single barrier per chunk: passing it proves every warp finished
        // chunk c-1's MMAs (program order), so refilling stage (c+1)&1 is safe
        __syncthreads();

        if (c + 1 < NCHUNK && t == 0) {
            const int sn_ = (c + 1) & 1;
            const uint32_t st = Sal + (uint32_t)sn_ * STAGE_BYTES;
            MBARRIER_EXPECT_TX(MB + sn_ * 8, STAGE_BYTES);
            bulk_cp(st,          srcA + (uint64_t)(c + 1) * CHB_PHI, 16384u, MB + sn_ * 8);
            bulk_cp(st + 16384u, srcB + (uint64_t)(c + 1) * CHB_X,   16384u, MB + sn_ * 8);
        }

        const uint32_t As = Sal + (uint32_t)s * STAGE_BYTES;
        uint32_t aaddr[4], baddr[2];
        #pragma unroll
        for (int im = 0; im < 4; im++) aaddr[im] = As + a_base[im];
        #pragma unroll
        for (int in_ = 0; in_ < 2; in_++) baddr[in_] = As + 16384u + b_base2[in_];

        #pragma unroll
        for (int ks = 0; ks < 4; ks++) {
            const uint32_t kx = (uint32_t)ks << 5;
            uint32_t a[4][4];
            #pragma unroll
            for (int im = 0; im < 4; im++)
                LDSM4(a[im][0], a[im][1], a[im][2], a[im][3], aaddr[im] ^ kx);
            uint32_t b[8];
            #pragma unroll
            for (int in_ = 0; in_ < 2; in_++)
                LDSM4(b[in_ * 4 + 0], b[in_ * 4 + 1], b[in_ * 4 + 2], b[in_ * 4 + 3],
                      baddr[in_] ^ kx);
            #pragma unroll
            for (int im = 0; im < 4; im++)
                #pragma unroll
                for (int ing = 0; ing < 4; ing++)
                    MMA16832H(acch[im][ing], a[im], b[ing * 2], b[ing * 2 + 1]);
        }
    }

    // ---------------- fused epilogue ----------------
    float pnl[4], pnh[4];
    #pragma unroll
    for (int im = 0; im < 4; im++) {
        pnl[im] = g_phinorm[k_base + m_off + im * 16 + (lane >> 2)] * L2E;
        pnh[im] = g_phinorm[k_base + m_off + im * 16 + (lane >> 2) + 8] * L2E;
    }
    float xnv[4][2];
    #pragma unroll
    for (int ing = 0; ing < 4; ing++)
        #pragma unroll
        for (int j = 0; j < 2; j++)
            xnv[ing][j] = g_xnorm[b_base + n_off + ing * 8 + (lane & 3) * 2 + j] * L2E;

    float sn[4][2];
    #pragma unroll
    for (int ing = 0; ing < 4; ing++) { sn[ing][0] = 0.0f; sn[ing][1] = 0.0f; }

    #pragma unroll
    for (int im = 0; im < 4; im++) {
        #pragma unroll
        for (int ing = 0; ing < 4; ing++) {
            const float2 v0 = __half22float2(*reinterpret_cast<__half2*>(&acch[im][ing][0]));
            const float2 v1 = __half22float2(*reinterpret_cast<__half2*>(&acch[im][ing][1]));
            sn[ing][0] += exp2_fast(fmaf(SINV, v0.x, -(pnl[im] + xnv[ing][0])));
            sn[ing][1] += exp2_fast(fmaf(SINV, v0.y, -(pnl[im] + xnv[ing][1])));
            sn[ing][0] += exp2_fast(fmaf(SINV, v1.x, -(pnh[im] + xnv[ing][0])));
            sn[ing][1] += exp2_fast(fmaf(SINV, v1.y, -(pnh[im] + xnv[ing][1])));
        }
    }
    #pragma unroll
    for (int off = 4; off < 32; off <<= 1)
        #pragma unroll
        for (int ing = 0; ing < 4; ing++)
            #pragma unroll
            for (int j = 0; j < 2; j++)
                sn[ing][j] += __shfl_xor_sync(0xffffffffu, sn[ing][j], off);

    if (lane < 4) {
        #pragma unroll
        for (int ing = 0; ing < 4; ing++)
            #pragma unroll
            for (int j = 0; j < 2; j++)
                atomicAdd(&g_colsum[b_base + n_off + ing * 8 + lane * 2 + j], sn[ing][j]);
    }

    // ---- last CTA of this b-slice finalizes its 128 columns ----
    __shared__ int is_last;
    __threadfence();
    if (t == 0) {
        const int old = atomicAdd(&g_cnt[blockIdx.x], 1);
        is_last = (old == (Kn / MTILE) - 1);
    }
    __syncthreads();
    if (is_last && t < NTILE) {
        float s = __logf(g_colsum[b_base + t] * (1.0f / (float)Kn) + 1e-9f)
                  * (1.0f / (float)Bn);
        #pragma unroll
        for (int off = 16; off > 0; off >>= 1)
            s += __shfl_xor_sync(0xffffffffu, s, off);
        if (lane == 0) atomicAdd(out, s);
    }
}

// ============================================================
extern "C" void kernel_launch(void* const* d_in, const int* in_sizes, int n_in,
                              void* d_out, int out_size)
{
    const float* x  = (const float*)d_in[0];
    const float* z  = (const float*)d_in[1];
    const float* W1 = (const float*)d_in[2];
    const float* b1 = (const float*)d_in[3];
    const float* W2 = (const float*)d_in[4];
    const float* b2 = (const float*)d_in[5];
    float* out = (float*)d_out;

    static int smem_set = 0;
    if (!smem_set) {
        cudaFuncSetAttribute(main_kernel, cudaFuncAttributeMaxDynamicSharedMemorySize,
                             SMEM_REQ);
        smem_set = 1;
    }

    prep_kernel<<<Bn / 8 + Kn, 256>>>(x, z, W1, b1, W2, b2, out);
    dim3 grid(Bn / NTILE, Kn / MTILE);   // (128, 4)
    main_kernel<<<grid, 256, SMEM_REQ>>>(out);
}

// round 17
// speedup vs baseline: 1.0449x; 1.0034x over previous
#include <cuda_runtime.h>
#include <cuda_bf16.h>
#include <cuda_fp16.h>
#include <math.h>
#include <cstdint>

#define Bn 16384
#define Dn 1024
#define Kn 512
#define Ln 128
#define Hn 64

#define MTILE 128
#define NTILE 256
#define DK    128            // fp8 elems per chunk (128B rows)
#define NCHUNK (Dn / DK)     // 8
#define STAGES 2
#define A_BYTES 16384u
#define B_BYTES 32768u
#define STAGE_BYTES (A_BYTES + B_BYTES)   // 48KB

#define CHB_X   ((uint64_t)Bn * 128)   // 2 MB per chunk block
#define CHB_PHI ((uint64_t)Kn * 128)   // 64 KB per chunk block

#define OFF_MBAR (STAGES * STAGE_BYTES)
#define SMEM_REQ (OFF_MBAR + 64 + 128)

#define L2E 1.4426950408889634f
#define SCALE 16.0f
#define SINV (2.0f * L2E / (SCALE * SCALE))

// ---------------- scratch (chunk-major, PRE-SWIZZLED) ----------------
__device__ uint8_t g_phi8[Kn * Dn];
__device__ uint8_t g_x8[Bn * Dn];
__device__ float g_phinorm[Kn];
__device__ float g_xnorm[Bn];
__device__ float g_colsum[Bn];
__device__ int   g_cnt[Bn / NTILE];

// ---------------- helpers ----------------
__device__ __forceinline__ uint32_t smem_u32(const void* p) {
    uint32_t a;
    asm("{ .reg .u64 t; cvta.to.shared.u64 t, %1; cvt.u32.u64 %0, t; }" : "=r"(a) : "l"(p));
    return a;
}

#define LDSM4(r0, r1, r2, r3, addr) \
    asm volatile("ldmatrix.sync.aligned.m8n8.x4.shared.b16 {%0,%1,%2,%3}, [%4];" \
                 : "=r"(r0), "=r"(r1), "=r"(r2), "=r"(r3) : "r"(addr))

// fp8 MMA with f16 accumulator: 2 acc regs (f16x2)
#define MMA16832H(d, a, b0, b1) \
    asm volatile("mma.sync.aligned.m16n8k32.row.col.f16.e4m3.e4m3.f16 " \
                 "{%0,%1}, {%2,%3,%4,%5}, {%6,%7}, {%0,%1};" \
                 : "+r"((d)[0]), "+r"((d)[1]) \
                 : "r"((a)[0]), "r"((a)[1]), "r"((a)[2]), "r"((a)[3]), \
                   "r"(b0), "r"(b1))

#define MBARRIER_INIT(mb, cnt) \
    asm volatile("mbarrier.init.shared.b64 [%0], %1;" :: "r"(mb), "r"(cnt) : "memory")
#define MBARRIER_EXPECT_TX(mb, bytes) \
    asm volatile("mbarrier.arrive.expect_tx.shared.b64 _, [%0], %1;" :: "r"(mb), "r"(bytes) : "memory")
#define MBARRIER_WAIT_PARITY(mb, ph) do {                                        \
    uint32_t _m = (mb); uint32_t _p = (ph); uint32_t _done;                      \
    asm volatile("{\n\t.reg .pred p;\n\t"                                        \
        "mbarrier.try_wait.parity.shared.b64 p, [%1], %2;\n\t"                   \
        "selp.b32 %0, 1, 0, p;\n\t}" : "=r"(_done) : "r"(_m), "r"(_p) : "memory");\
    if (!_done) {                                                                \
        asm volatile("{\n\t.reg .pred P1;\n\t"                                   \
        "WL_%=:\n\t"                                                             \
        "mbarrier.try_wait.parity.shared.b64 P1, [%0], %1, 0x989680;\n\t"        \
        "@P1 bra.uni WD_%=;\n\t"                                                 \
        "bra.uni WL_%=;\n\t"                                                     \
        "WD_%=:\n\t}" :: "r"(_m), "r"(_p) : "memory");                           \
    }                                                                            \
} while (0)

__device__ __forceinline__ void bulk_cp(uint32_t dst, const void* src,
                                        uint32_t bytes, uint32_t mbar) {
    asm volatile(
        "cp.async.bulk.shared::cluster.global.mbarrier::complete_tx::bytes "
        "[%0], [%1], %2, [%3];"
        :: "r"(dst), "l"(src), "r"(bytes), "r"(mbar) : "memory");
}

__device__ __forceinline__ uint32_t pack_e4m3x4(float e0, float e1, float e2, float e3) {
    uint16_t lo, hi;
    asm("cvt.rn.satfinite.e4m3x2.f32 %0, %1, %2;" : "=h"(lo) : "f"(e1), "f"(e0));
    asm("cvt.rn.satfinite.e4m3x2.f32 %0, %1, %2;" : "=h"(hi) : "f"(e3), "f"(e2));
    return (uint32_t)lo | ((uint32_t)hi << 16);
}

// fast 2^t, FFMA-only. deg-4 poly on [-0.5, 0.5]
__device__ __forceinline__ float exp2_fast(float t) {
    t = fmaxf(t, -126.0f);
    const int   i = __float2int_rn(t);
    const float f = t - (float)i;
    float p = fmaf(0.0096181291f, f, 0.0555041087f);
    p = fmaf(p, f, 0.2402265069f);
    p = fmaf(p, f, 0.6931471806f);
    p = fmaf(p, f, 1.0f);
    return p * __int_as_float((i + 127) << 23);
}

// ============================================================
// Kernel 1 (prep): blocks [0, 2048) = x (warp per row, coalesced);
//                  blocks [2048, 2048+Kn) = phi MLP
// ============================================================
__global__ __launch_bounds__(256) void prep_kernel(
    const float* __restrict__ x,  const float* __restrict__ z,
    const float* __restrict__ W1, const float* __restrict__ b1,
    const float* __restrict__ W2, const float* __restrict__ b2,
    float* __restrict__ out)
{
    const int t = threadIdx.x;

    if (blockIdx.x < Bn / 8) {
        const int lane = t & 31;
        const int b = blockIdx.x * 8 + (t >> 5);
        const float* xr = x + (uint64_t)b * Dn;
        const uint32_t rowoff = ((((lane >> 2) ^ (b & 7)) << 4) | ((lane & 3) << 2));
        uint8_t* xo = g_x8 + (uint64_t)b * 128 + rowoff;
        float nrm = 0.0f;
        #pragma unroll
        for (int i = 0; i < 8; i++) {
            const float4 v = *reinterpret_cast<const float4*>(xr + i * 128 + lane * 4);
            *reinterpret_cast<uint32_t*>(xo + i * CHB_X) =
                pack_e4m3x4(v.x * SCALE, v.y * SCALE, v.z * SCALE, v.w * SCALE);
            nrm = fmaf(v.x, v.x, nrm);
            nrm = fmaf(v.y, v.y, nrm);
            nrm = fmaf(v.z, v.z, nrm);
            nrm = fmaf(v.w, v.w, nrm);
        }
        #pragma unroll
        for (int off = 16; off > 0; off >>= 1)
            nrm += __shfl_xor_sync(0xffffffffu, nrm, off);
        if (lane == 0) {
            g_xnorm[b] = nrm;
            g_colsum[b] = 0.0f;
            if (b < Bn / NTILE) g_cnt[b] = 0;
            if (b == 0) out[0] = 0.0f;
        }
    } else {
        __shared__ float zrow[Ln];
        __shared__ float hidden[Hn];
        __shared__ float red[256];
        const int k = blockIdx.x - Bn / 8;

        if (t < Ln) zrow[t] = z[k * Ln + t];
        __syncthreads();

        if (t < Hn) {
            float acc = b1[t];
            #pragma unroll 8
            for (int l = 0; l < Ln; l++)
                acc = fmaf(zrow[l], W1[l * Hn + t], acc);
            hidden[t] = fmaxf(acc, 0.0f);
        }
        __syncthreads();

        const int d0 = t * 4;
        float4 acc = make_float4(b2[d0], b2[d0 + 1], b2[d0 + 2], b2[d0 + 3]);
        #pragma unroll 8
        for (int h = 0; h < Hn; h++) {
            const float hv = hidden[h];
            const float4 w = *reinterpret_cast<const float4*>(W2 + h * Dn + d0);
            acc.x = fmaf(hv, w.x, acc.x);
            acc.y = fmaf(hv, w.y, acc.y);
            acc.z = fmaf(hv, w.z, acc.z);
            acc.w = fmaf(hv, w.w, acc.w);
        }
        {
            const int chunk = t >> 5;
            const uint32_t rowoff = (((((t >> 2) & 7) ^ (k & 7)) << 4) | ((t & 3) << 2));
            *reinterpret_cast<uint32_t*>(
                g_phi8 + (uint64_t)chunk * CHB_PHI + (uint64_t)k * 128 + rowoff) =
                pack_e4m3x4(acc.x * SCALE, acc.y * SCALE, acc.z * SCALE, acc.w * SCALE);
        }

        red[t] = acc.x * acc.x + acc.y * acc.y + acc.z * acc.z + acc.w * acc.w;
        __syncthreads();
        for (int s = 128; s > 0; s >>= 1) {
            if (t < s) red[t] += red[t + s];
            __syncthreads();
        }
        if (t == 0) g_phinorm[k] = red[0];
    }
}

// ============================================================
// Kernel 2 (main): fp8 mma (f16 acc) GEMM 128k x 256b tile,
//   2-stage bulk-TMA, warp tile 64m x 64n (4 MMA per LDSM)
// ============================================================
__global__ __launch_bounds__(256, 2) void main_kernel(float* __restrict__ out)
{
    extern __shared__ char smem[];
    const uint32_t Sal = (smem_u32(smem) + 127u) & ~127u;
    const uint32_t MB  = Sal + OFF_MBAR;

    const int t    = threadIdx.x;
    const int lane = t & 31;
    const int wid  = t >> 5;
    const int b_base = blockIdx.x * NTILE;
    const int k_base = blockIdx.y * MTILE;

    const int m_off = (wid & 1) * 64;     // 2-way m
    const int n_off = (wid >> 1) * 64;    // 4-way n (64 cols per warp)

    const uint8_t* srcA = g_phi8 + (uint64_t)k_base * 128;
    const uint8_t* srcB = g_x8   + (uint64_t)b_base * 128;

    if (t == 0) {
        MBARRIER_INIT(MB + 0, 1);
        MBARRIER_INIT(MB + 8, 1);
        asm volatile("fence.proxy.async.shared::cta;" ::: "memory");
    }
    __syncthreads();

    // prologue: stage chunk 0 into buffer 0
    if (t == 0) {
        MBARRIER_EXPECT_TX(MB + 0, STAGE_BYTES);
        bulk_cp(Sal,           srcA, A_BYTES, MB + 0);
        bulk_cp(Sal + A_BYTES, srcB, B_BYTES, MB + 0);
    }

    // ---- loop-invariant LDSM base offsets ----
    uint32_t a_base[4], b_base2[4];
    {
        const int hi = lane >> 4;
        #pragma unroll
        for (int im = 0; im < 4; im++) {
            const int arow = m_off + im * 16 + (lane & 15);
            const int r = arow & 7;
            a_base[im] = (uint32_t)(arow * 128 + ((hi ^ (r & 1)) << 4) + ((r & 6) << 4));
        }
        const int g  = lane >> 3;
        const int rb = lane & 7;
        #pragma unroll
        for (int in_ = 0; in_ < 4; in_++) {
            const int nrow = n_off + in_ * 16 + ((g >> 1) << 3) + rb;
            b_base2[in_] = (uint32_t)(nrow * 128 + (((g & 1) ^ (rb & 1)) << 4) + ((rb & 6) << 4));
        }
    }

    // f16x2 accumulators: [im 4][ing 8][2]
    uint32_t acch[4][8][2];
    #pragma unroll
    for (int i = 0; i < 4; i++)
        #pragma unroll
        for (int j = 0; j < 8; j++) { acch[i][j][0] = 0u; acch[i][j][1] = 0u; }

    int ph0 = 0, ph1 = 0;

    for (int c = 0; c < NCHUNK; c++) {
        const int s = c & 1;
        if (s == 0) { MBARRIER_WAIT_PARITY(MB + 0, (uint32_t)ph0); ph0 ^= 1; }
        else        { MBARRIER_WAIT_PARITY(MB + 8, (uint32_t)ph1); ph1 ^= 1; }
        __syncthreads();   // proves chunk c-1 fully consumed -> refill safe

        if (c + 1 < NCHUNK && t == 0) {
            const int sn_ = (c + 1) & 1;
            const uint32_t st = Sal + (uint32_t)sn_ * STAGE_BYTES;
            MBARRIER_EXPECT_TX(MB + sn_ * 8, STAGE_BYTES);
            bulk_cp(st,           srcA + (uint64_t)(c + 1) * CHB_PHI, A_BYTES, MB + sn_ * 8);
            bulk_cp(st + A_BYTES, srcB + (uint64_t)(c + 1) * CHB_X,   B_BYTES, MB + sn_ * 8);
        }

        const uint32_t As = Sal + (uint32_t)s * STAGE_BYTES;
        uint32_t aaddr[4], baddr[4];
        #pragma unroll
        for (int im = 0; im < 4; im++) aaddr[im] = As + a_base[im];
        #pragma unroll
        for (int in_ = 0; in_ < 4; in_++) baddr[in_] = As + A_BYTES + b_base2[in_];

        #pragma unroll
        for (int ks = 0; ks < 4; ks++) {
            const uint32_t kx = (uint32_t)ks << 5;
            uint32_t a[4][4];
            #pragma unroll
            for (int im = 0; im < 4; im++)
                LDSM4(a[im][0], a[im][1], a[im][2], a[im][3], aaddr[im] ^ kx);
            uint32_t b[16];
            #pragma unroll
            for (int in_ = 0; in_ < 4; in_++)
                LDSM4(b[in_ * 4 + 0], b[in_ * 4 + 1], b[in_ * 4 + 2], b[in_ * 4 + 3],
                      baddr[in_] ^ kx);
            #pragma unroll
            for (int im = 0; im < 4; im++)
                #pragma unroll
                for (int ing = 0; ing < 8; ing++)
                    MMA16832H(acch[im][ing], a[im], b[ing * 2], b[ing * 2 + 1]);
        }
    }

    // ---------------- fused epilogue ----------------
    float pnl[4], pnh[4];
    #pragma unroll
    for (int im = 0; im < 4; im++) {
        pnl[im] = g_phinorm[k_base + m_off + im * 16 + (lane >> 2)] * L2E;
        pnh[im] = g_phinorm[k_base + m_off + im * 16 + (lane >> 2) + 8] * L2E;
    }
    float xnv[8][2];
    #pragma unroll
    for (int ing = 0; ing < 8; ing++)
        #pragma unroll
        for (int j = 0; j < 2; j++)
            xnv[ing][j] = g_xnorm[b_base + n_off + ing * 8 + (lane & 3) * 2 + j] * L2E;

    float sn[8][2];
    #pragma unroll
    for (int ing = 0; ing < 8; ing++) { sn[ing][0] = 0.0f; sn[ing][1] = 0.0f; }

    #pragma unroll
    for (int im = 0; im < 4; im++) {
        #pragma unroll
        for (int ing = 0; ing < 8; ing++) {
            const float2 v0 = __half22float2(*reinterpret_cast<__half2*>(&acch[im][ing][0]));
            const float2 v1 = __half22float2(*reinterpret_cast<__half2*>(&acch[im][ing][1]));
            sn[ing][0] += exp2_fast(fmaf(SINV, v0.x, -(pnl[im] + xnv[ing][0])));
            sn[ing][1] += exp2_fast(fmaf(SINV, v0.y, -(pnl[im] + xnv[ing][1])));
            sn[ing][0] += exp2_fast(fmaf(SINV, v1.x, -(pnh[im] + xnv[ing][0])));
            sn[ing][1] += exp2_fast(fmaf(SINV, v1.y, -(pnh[im] + xnv[ing][1])));
        }
    }
    #pragma unroll
    for (int off = 4; off < 32; off <<= 1)
        #pragma unroll
        for (int ing = 0; ing < 8; ing++)
            #pragma unroll
            for (int j = 0; j < 2; j++)
                sn[ing][j] += __shfl_xor_sync(0xffffffffu, sn[ing][j], off);

    if (lane < 4) {
        #pragma unroll
        for (int ing = 0; ing < 8; ing++)
            #pragma unroll
            for (int j = 0; j < 2; j++)
                atomicAdd(&g_colsum[b_base + n_off + ing * 8 + lane * 2 + j], sn[ing][j]);
    }

    // ---- last CTA of this b-slice finalizes its 256 columns ----
    __shared__ int is_last;
    __threadfence();
    if (t == 0) {
        const int old = atomicAdd(&g_cnt[blockIdx.x], 1);
        is_last = (old == (Kn / MTILE) - 1);
    }
    __syncthreads();
    if (is_last) {
        float s = __logf(g_colsum[b_base + t] * (1.0f / (float)Kn) + 1e-9f)
                  * (1.0f / (float)Bn);
        #pragma unroll
        for (int off = 16; off > 0; off >>= 1)
            s += __shfl_xor_sync(0xffffffffu, s, off);
        if (lane == 0) atomicAdd(out, s);
    }
}

// ============================================================
extern "C" void kernel_launch(void* const* d_in, const int* in_sizes, int n_in,
                              void* d_out, int out_size)
{
    const float* x  = (const float*)d_in[0];
    const float* z  = (const float*)d_in[1];
    const float* W1 = (const float*)d_in[2];
    const float* b1 = (const float*)d_in[3];
    const float* W2 = (const float*)d_in[4];
    const float* b2 = (const float*)d_in[5];
    float* out = (float*)d_out;

    static int smem_set = 0;
    if (!smem_set) {
        cudaFuncSetAttribute(main_kernel, cudaFuncAttributeMaxDynamicSharedMemorySize,
                             SMEM_REQ);
        smem_set = 1;
    }

    prep_kernel<<<Bn / 8 + Kn, 256>>>(x, z, W1, b1, W2, b2, out);
    dim3 grid(Bn / NTILE, Kn / MTILE);   // (64, 4)
    main_kernel<<<grid, 256, SMEM_REQ>>>(out);
}